// round 1
// baseline (speedup 1.0000x reference)
#include <cuda_runtime.h>
#include <math.h>

// Problem constants (fixed by the reference: B=8, H=W=128, DIM=128, HEADS=4, HD=32, MLP=512, DEPTH=4)
#define MTOT 131072          // 8 * 16384 tokens
#define SPATIAL 128

// Scratch (static device globals: allocation-free, graph-capture safe)
__device__ float g_qkv[(size_t)MTOT * 384];   // [token][q(128) | k(128) | v(128)], inner = head*32 + c
__device__ float g_o  [(size_t)MTOT * 128];   // attention output, merged heads
__device__ float g_h  [(size_t)MTOT * 512];   // MLP hidden

__device__ __forceinline__ float gelu_exact(float a) {
    return 0.5f * a * (1.0f + erff(a * 0.70710678118654752440f));
}

// ---------------------------------------------------------------------------
// Kernel 1: y = LN1(x); qkv = y @ Wqkv   (M=131072, K=128, N=384)
// CTA: 64 tokens, 256 threads. A (LN output) staged k-major in smem; N in 6 chunks of 64.
// ---------------------------------------------------------------------------
__global__ __launch_bounds__(256) void k_ln1_qkv(
    const float* __restrict__ X, const float* __restrict__ gamma,
    const float* __restrict__ beta, const float* __restrict__ W)
{
    extern __shared__ float sm[];
    float (*A)[64]  = (float (*)[64])sm;            // [128][64] k-major
    float (*Bs)[64] = (float (*)[64])(sm + 8192);   // [128][64]
    const int tid = threadIdx.x;
    const int m0  = blockIdx.x * 64;

    // ---- LayerNorm of 64 tokens, transposed into A ----
    {
        const int t  = tid >> 2;
        const int cs = (tid & 3) * 32;
        const float4* xr = (const float4*)(X + (size_t)(m0 + t) * 128 + cs);
        float v[32]; float s = 0.f, sq = 0.f;
#pragma unroll
        for (int i = 0; i < 8; i++) {
            float4 f = xr[i];
            v[4*i+0]=f.x; v[4*i+1]=f.y; v[4*i+2]=f.z; v[4*i+3]=f.w;
            s  += f.x + f.y + f.z + f.w;
            sq += f.x*f.x + f.y*f.y + f.z*f.z + f.w*f.w;
        }
        s  += __shfl_xor_sync(0xffffffffu, s , 1);
        sq += __shfl_xor_sync(0xffffffffu, sq, 1);
        s  += __shfl_xor_sync(0xffffffffu, s , 2);
        sq += __shfl_xor_sync(0xffffffffu, sq, 2);
        const float mean = s * (1.f/128.f);
        const float rstd = rsqrtf(sq*(1.f/128.f) - mean*mean + 1e-3f);
#pragma unroll
        for (int i = 0; i < 32; i++) {
            const int k = cs + i;
            A[k][t] = (v[i] - mean) * rstd * gamma[k] + beta[k];
        }
    }

    const int ty = tid >> 4, tx = tid & 15;
    float* outp = g_qkv + (size_t)m0 * 384;
    for (int nc = 0; nc < 6; nc++) {
        __syncthreads();
#pragma unroll
        for (int i = 0; i < 8; i++) {
            const int idx = tid + i * 256;
            const int k = idx >> 4, n4 = idx & 15;
            ((float4*)Bs[k])[n4] = ((const float4*)(W + k*384 + nc*64))[n4];
        }
        __syncthreads();
        float acc[4][4] = {};
#pragma unroll 8
        for (int k = 0; k < 128; k++) {
            const float4 a = *(const float4*)&A[k][ty*4];
            const float4 b = *(const float4*)&Bs[k][tx*4];
            acc[0][0]+=a.x*b.x; acc[0][1]+=a.x*b.y; acc[0][2]+=a.x*b.z; acc[0][3]+=a.x*b.w;
            acc[1][0]+=a.y*b.x; acc[1][1]+=a.y*b.y; acc[1][2]+=a.y*b.z; acc[1][3]+=a.y*b.w;
            acc[2][0]+=a.z*b.x; acc[2][1]+=a.z*b.y; acc[2][2]+=a.z*b.z; acc[2][3]+=a.z*b.w;
            acc[3][0]+=a.w*b.x; acc[3][1]+=a.w*b.y; acc[3][2]+=a.w*b.z; acc[3][3]+=a.w*b.w;
        }
#pragma unroll
        for (int i = 0; i < 4; i++) {
            *(float4*)(outp + (size_t)(ty*4+i)*384 + nc*64 + tx*4) =
                make_float4(acc[i][0], acc[i][1], acc[i][2], acc[i][3]);
        }
    }
}

// ---------------------------------------------------------------------------
// Kernel 2: local 3x3 attention. CTA = 16x16 spatial tile of one image,
// loops 4 heads; K/V halo (18x18, zero-padded like the reference) in smem.
// One thread per token. Padded stride 36 avoids smem bank conflicts.
// ---------------------------------------------------------------------------
__global__ __launch_bounds__(256) void k_attn()
{
    extern __shared__ float sm[];
    float* ksh = sm;              // 18*18*36 = 11664 floats
    float* vsh = sm + 11664;
    float* qo  = sm + 2*11664;    // 256*36 = 9216 floats
    const int tid = threadIdx.x;
    const int b   = blockIdx.z;
    const int ti0 = blockIdx.y * 16, tj0 = blockIdx.x * 16;
    const size_t img_base = (size_t)b * (SPATIAL * SPATIAL);

    for (int head = 0; head < 4; head++) {
        if (head) __syncthreads();
        const int qoff = head*32, koff = 128 + head*32, voff = 256 + head*32;

        // halo K/V (zeros outside the image, matching reference zero-pad)
        for (int idx = tid; idx < 18*18*32; idx += 256) {
            const int c  = idx & 31;
            const int rc = idx >> 5;
            const int r  = rc / 18, cl = rc % 18;
            const int gi = ti0 + r - 1, gj = tj0 + cl - 1;
            float kv = 0.f, vv = 0.f;
            if (gi >= 0 && gi < SPATIAL && gj >= 0 && gj < SPATIAL) {
                const float* p = g_qkv + (img_base + (size_t)gi*SPATIAL + gj) * 384;
                kv = p[koff + c]; vv = p[voff + c];
            }
            ksh[rc*36 + c] = kv;
            vsh[rc*36 + c] = vv;
        }
        // q tile (coalesced)
        for (int idx = tid; idx < 256*32; idx += 256) {
            const int c = idx & 31, t = idx >> 5;
            const int gi = ti0 + (t >> 4), gj = tj0 + (t & 15);
            qo[t*36 + c] = g_qkv[(img_base + (size_t)gi*SPATIAL + gj)*384 + qoff + c];
        }
        __syncthreads();

        const int t = tid, lti = t >> 4, ltj = t & 15;
        float q[32];
#pragma unroll
        for (int i = 0; i < 8; i++) {
            float4 f = *(const float4*)&qo[t*36 + i*4];
            q[4*i+0]=f.x; q[4*i+1]=f.y; q[4*i+2]=f.z; q[4*i+3]=f.w;
        }
        float lg[9];
#pragma unroll
        for (int nb = 0; nb < 9; nb++) {
            const float* kp = &ksh[((lti + nb/3)*18 + (ltj + nb%3))*36];
            float d = 0.f;
#pragma unroll
            for (int i = 0; i < 8; i++) {
                float4 f = *(const float4*)&kp[i*4];
                d += q[4*i]*f.x + q[4*i+1]*f.y + q[4*i+2]*f.z + q[4*i+3]*f.w;
            }
            lg[nb] = d * 0.17677669529663687f;   // 32^-0.5
        }
        float mx = lg[0];
#pragma unroll
        for (int nb = 1; nb < 9; nb++) mx = fmaxf(mx, lg[nb]);
        float p[9], Z = 0.f;
#pragma unroll
        for (int nb = 0; nb < 9; nb++) { p[nb] = expf(lg[nb] - mx); Z += p[nb]; }
        const float inv = 1.f / Z;
        float o[32] = {};
#pragma unroll
        for (int nb = 0; nb < 9; nb++) {
            const float wgt = p[nb] * inv;
            const float* vp = &vsh[((lti + nb/3)*18 + (ltj + nb%3))*36];
#pragma unroll
            for (int i = 0; i < 8; i++) {
                float4 f = *(const float4*)&vp[i*4];
                o[4*i+0] += wgt*f.x; o[4*i+1] += wgt*f.y;
                o[4*i+2] += wgt*f.z; o[4*i+3] += wgt*f.w;
            }
        }
        // stage own row (no cross-thread hazard: each thread reads/writes only row t)
#pragma unroll
        for (int i = 0; i < 8; i++)
            *(float4*)&qo[t*36 + i*4] = make_float4(o[4*i], o[4*i+1], o[4*i+2], o[4*i+3]);
        __syncthreads();
        // coalesced writeout
        for (int idx = tid; idx < 256*32; idx += 256) {
            const int c = idx & 31, tt = idx >> 5;
            const int gi = ti0 + (tt >> 4), gj = tj0 + (tt & 15);
            g_o[(img_base + (size_t)gi*SPATIAL + gj)*128 + head*32 + c] = qo[tt*36 + c];
        }
    }
}

// ---------------------------------------------------------------------------
// Kernel 3: x += o @ out_w + out_b   (K=128, N=128 in 2 chunks)
// ---------------------------------------------------------------------------
__global__ __launch_bounds__(256) void k_proj_res(
    const float* __restrict__ W, const float* __restrict__ bias, float* __restrict__ X)
{
    extern __shared__ float sm[];
    float (*A)[64]  = (float (*)[64])sm;
    float (*Bs)[64] = (float (*)[64])(sm + 8192);
    const int tid = threadIdx.x;
    const int m0  = blockIdx.x * 64;
    {
        const int t = tid >> 2, cs = (tid & 3) * 32;
        const float4* orow = (const float4*)(g_o + (size_t)(m0 + t)*128 + cs);
#pragma unroll
        for (int i = 0; i < 8; i++) {
            float4 f = orow[i];
            A[cs+4*i+0][t]=f.x; A[cs+4*i+1][t]=f.y; A[cs+4*i+2][t]=f.z; A[cs+4*i+3][t]=f.w;
        }
    }
    const int ty = tid >> 4, tx = tid & 15;
    for (int nc = 0; nc < 2; nc++) {
        __syncthreads();
#pragma unroll
        for (int i = 0; i < 8; i++) {
            const int idx = tid + i*256;
            const int k = idx >> 4, n4 = idx & 15;
            ((float4*)Bs[k])[n4] = ((const float4*)(W + k*128 + nc*64))[n4];
        }
        __syncthreads();
        float acc[4][4] = {};
#pragma unroll 8
        for (int k = 0; k < 128; k++) {
            const float4 a = *(const float4*)&A[k][ty*4];
            const float4 b = *(const float4*)&Bs[k][tx*4];
            acc[0][0]+=a.x*b.x; acc[0][1]+=a.x*b.y; acc[0][2]+=a.x*b.z; acc[0][3]+=a.x*b.w;
            acc[1][0]+=a.y*b.x; acc[1][1]+=a.y*b.y; acc[1][2]+=a.y*b.z; acc[1][3]+=a.y*b.w;
            acc[2][0]+=a.z*b.x; acc[2][1]+=a.z*b.y; acc[2][2]+=a.z*b.z; acc[2][3]+=a.z*b.w;
            acc[3][0]+=a.w*b.x; acc[3][1]+=a.w*b.y; acc[3][2]+=a.w*b.z; acc[3][3]+=a.w*b.w;
        }
        const float4 bb = *(const float4*)(bias + nc*64 + tx*4);
#pragma unroll
        for (int i = 0; i < 4; i++) {
            float* xp = X + (size_t)(m0+ty*4+i)*128 + nc*64 + tx*4;
            float4 xo = *(float4*)xp;
            *(float4*)xp = make_float4(acc[i][0]+xo.x+bb.x, acc[i][1]+xo.y+bb.y,
                                       acc[i][2]+xo.z+bb.z, acc[i][3]+xo.w+bb.w);
        }
    }
}

// ---------------------------------------------------------------------------
// Kernel 4: y = LN2(x); h = gelu(y @ W1 + b1)   (K=128, N=512 in 8 chunks)
// ---------------------------------------------------------------------------
__global__ __launch_bounds__(256) void k_ln2_ff1(
    const float* __restrict__ X, const float* __restrict__ gamma,
    const float* __restrict__ beta, const float* __restrict__ W,
    const float* __restrict__ bias)
{
    extern __shared__ float sm[];
    float (*A)[64]  = (float (*)[64])sm;
    float (*Bs)[64] = (float (*)[64])(sm + 8192);
    const int tid = threadIdx.x;
    const int m0  = blockIdx.x * 64;
    {
        const int t = tid >> 2, cs = (tid & 3) * 32;
        const float4* xr = (const float4*)(X + (size_t)(m0 + t)*128 + cs);
        float v[32]; float s = 0.f, sq = 0.f;
#pragma unroll
        for (int i = 0; i < 8; i++) {
            float4 f = xr[i];
            v[4*i+0]=f.x; v[4*i+1]=f.y; v[4*i+2]=f.z; v[4*i+3]=f.w;
            s  += f.x + f.y + f.z + f.w;
            sq += f.x*f.x + f.y*f.y + f.z*f.z + f.w*f.w;
        }
        s  += __shfl_xor_sync(0xffffffffu, s , 1);
        sq += __shfl_xor_sync(0xffffffffu, sq, 1);
        s  += __shfl_xor_sync(0xffffffffu, s , 2);
        sq += __shfl_xor_sync(0xffffffffu, sq, 2);
        const float mean = s * (1.f/128.f);
        const float rstd = rsqrtf(sq*(1.f/128.f) - mean*mean + 1e-3f);
#pragma unroll
        for (int i = 0; i < 32; i++) {
            const int k = cs + i;
            A[k][t] = (v[i] - mean) * rstd * gamma[k] + beta[k];
        }
    }
    const int ty = tid >> 4, tx = tid & 15;
    float* outp = g_h + (size_t)m0 * 512;
    for (int nc = 0; nc < 8; nc++) {
        __syncthreads();
#pragma unroll
        for (int i = 0; i < 8; i++) {
            const int idx = tid + i*256;
            const int k = idx >> 4, n4 = idx & 15;
            ((float4*)Bs[k])[n4] = ((const float4*)(W + k*512 + nc*64))[n4];
        }
        __syncthreads();
        float acc[4][4] = {};
#pragma unroll 8
        for (int k = 0; k < 128; k++) {
            const float4 a = *(const float4*)&A[k][ty*4];
            const float4 b = *(const float4*)&Bs[k][tx*4];
            acc[0][0]+=a.x*b.x; acc[0][1]+=a.x*b.y; acc[0][2]+=a.x*b.z; acc[0][3]+=a.x*b.w;
            acc[1][0]+=a.y*b.x; acc[1][1]+=a.y*b.y; acc[1][2]+=a.y*b.z; acc[1][3]+=a.y*b.w;
            acc[2][0]+=a.z*b.x; acc[2][1]+=a.z*b.y; acc[2][2]+=a.z*b.z; acc[2][3]+=a.z*b.w;
            acc[3][0]+=a.w*b.x; acc[3][1]+=a.w*b.y; acc[3][2]+=a.w*b.z; acc[3][3]+=a.w*b.w;
        }
        const float4 bb = *(const float4*)(bias + nc*64 + tx*4);
#pragma unroll
        for (int i = 0; i < 4; i++) {
            *(float4*)(outp + (size_t)(ty*4+i)*512 + nc*64 + tx*4) =
                make_float4(gelu_exact(acc[i][0]+bb.x), gelu_exact(acc[i][1]+bb.y),
                            gelu_exact(acc[i][2]+bb.z), gelu_exact(acc[i][3]+bb.w));
        }
    }
}

// ---------------------------------------------------------------------------
// Kernel 5: x += h @ W2 + b2   (K=512 tiled by 128, N=128 in one pass)
// ---------------------------------------------------------------------------
#define FMA4P(p, av, bv) { (p)[0]+=(av)*(bv).x; (p)[1]+=(av)*(bv).y; (p)[2]+=(av)*(bv).z; (p)[3]+=(av)*(bv).w; }

__global__ __launch_bounds__(256) void k_ff2_res(
    const float* __restrict__ W, const float* __restrict__ bias, float* __restrict__ X)
{
    extern __shared__ float sm[];
    float (*A)[64]   = (float (*)[64])sm;            // [128][64]
    float (*Bs)[128] = (float (*)[128])(sm + 8192);  // [128][128]
    const int tid = threadIdx.x;
    const int m0  = blockIdx.x * 64;
    const int t = tid >> 2, cs = (tid & 3) * 32;
    const int ty = tid >> 4, tx = tid & 15;
    float acc[4][8] = {};

    for (int kt = 0; kt < 4; kt++) {
        if (kt) __syncthreads();
        const float4* hr = (const float4*)(g_h + (size_t)(m0 + t)*512 + kt*128 + cs);
#pragma unroll
        for (int i = 0; i < 8; i++) {
            float4 f = hr[i];
            A[cs+4*i+0][t]=f.x; A[cs+4*i+1][t]=f.y; A[cs+4*i+2][t]=f.z; A[cs+4*i+3][t]=f.w;
        }
#pragma unroll
        for (int i = 0; i < 16; i++) {
            const int idx = tid + i*256;
            const int k = idx >> 5, n4 = idx & 31;
            ((float4*)Bs[k])[n4] = ((const float4*)(W + (size_t)(kt*128 + k)*128))[n4];
        }
        __syncthreads();
#pragma unroll 4
        for (int k = 0; k < 128; k++) {
            const float4 a  = *(const float4*)&A[k][ty*4];
            const float4 b0 = *(const float4*)&Bs[k][tx*4];
            const float4 b1 = *(const float4*)&Bs[k][tx*4 + 64];
            FMA4P(acc[0],   a.x, b0); FMA4P(acc[0]+4, a.x, b1);
            FMA4P(acc[1],   a.y, b0); FMA4P(acc[1]+4, a.y, b1);
            FMA4P(acc[2],   a.z, b0); FMA4P(acc[2]+4, a.z, b1);
            FMA4P(acc[3],   a.w, b0); FMA4P(acc[3]+4, a.w, b1);
        }
    }
    const float4 bb0 = *(const float4*)(bias + tx*4);
    const float4 bb1 = *(const float4*)(bias + 64 + tx*4);
#pragma unroll
    for (int i = 0; i < 4; i++) {
        float* xrow = X + (size_t)(m0 + ty*4 + i)*128;
        float4 x0 = *(float4*)(xrow + tx*4);
        float4 x1 = *(float4*)(xrow + 64 + tx*4);
        *(float4*)(xrow + tx*4) = make_float4(acc[i][0]+x0.x+bb0.x, acc[i][1]+x0.y+bb0.y,
                                              acc[i][2]+x0.z+bb0.z, acc[i][3]+x0.w+bb0.w);
        *(float4*)(xrow + 64 + tx*4) = make_float4(acc[i][4]+x1.x+bb1.x, acc[i][5]+x1.y+bb1.y,
                                                   acc[i][6]+x1.z+bb1.z, acc[i][7]+x1.w+bb1.w);
    }
}

// ---------------------------------------------------------------------------
// Host launcher
// ---------------------------------------------------------------------------
extern "C" void kernel_launch(void* const* d_in, const int* in_sizes, int n_in,
                              void* d_out, int out_size)
{
    (void)in_sizes; (void)n_in; (void)out_size;
    const float* x_in  = (const float*)d_in[0];
    const float* ln1_g = (const float*)d_in[1];
    const float* ln1_b = (const float*)d_in[2];
    const float* qkv_w = (const float*)d_in[3];
    const float* out_w = (const float*)d_in[4];
    const float* out_b = (const float*)d_in[5];
    const float* ln2_g = (const float*)d_in[6];
    const float* ln2_b = (const float*)d_in[7];
    const float* ff_w1 = (const float*)d_in[8];
    const float* ff_b1 = (const float*)d_in[9];
    const float* ff_w2 = (const float*)d_in[10];
    const float* ff_b2 = (const float*)d_in[11];
    float* X = (float*)d_out;

    const int SM_GEMM = 65536;                      // 2 * 128*64 floats
    const int SM_FF2  = (8192 + 16384) * 4;         // 98304
    const int SM_ATTN = (2*11664 + 9216) * 4;       // 130176
    cudaFuncSetAttribute(k_ln1_qkv, cudaFuncAttributeMaxDynamicSharedMemorySize, SM_GEMM);
    cudaFuncSetAttribute(k_proj_res, cudaFuncAttributeMaxDynamicSharedMemorySize, SM_GEMM);
    cudaFuncSetAttribute(k_ln2_ff1, cudaFuncAttributeMaxDynamicSharedMemorySize, SM_GEMM);
    cudaFuncSetAttribute(k_ff2_res, cudaFuncAttributeMaxDynamicSharedMemorySize, SM_FF2);
    cudaFuncSetAttribute(k_attn,    cudaFuncAttributeMaxDynamicSharedMemorySize, SM_ATTN);

    cudaMemcpyAsync(X, x_in, (size_t)MTOT * 128 * sizeof(float),
                    cudaMemcpyDeviceToDevice, 0);

    const int GEMM_BLOCKS = MTOT / 64;   // 2048
    dim3 gAttn(8, 8, 8);                 // (tj, ti, batch) 16x16 tiles
    for (int d = 0; d < 4; d++) {
        k_ln1_qkv<<<GEMM_BLOCKS, 256, SM_GEMM>>>(X, ln1_g + d*128, ln1_b + d*128,
                                                 qkv_w + (size_t)d*128*384);
        k_attn<<<gAttn, 256, SM_ATTN>>>();
        k_proj_res<<<GEMM_BLOCKS, 256, SM_GEMM>>>(out_w + (size_t)d*128*128,
                                                  out_b + d*128, X);
        k_ln2_ff1<<<GEMM_BLOCKS, 256, SM_GEMM>>>(X, ln2_g + d*128, ln2_b + d*128,
                                                 ff_w1 + (size_t)d*128*512, ff_b1 + d*512);
        k_ff2_res<<<GEMM_BLOCKS, 256, SM_FF2>>>(ff_w2 + (size_t)d*512*128,
                                                ff_b2 + d*128, X);
    }
}